// round 14
// baseline (speedup 1.0000x reference)
#include <cuda_runtime.h>
#include <cuda_fp16.h>
#include <cstdint>

#define S_LEN   2048
#define BATCH   2
#define DMODEL  1024
#define NHEADS  16
#define DK      64
#define MTOT    (BATCH * S_LEN)   // 4096

// ---------------- scratch (static device globals; no dynamic allocation) ----
__device__ __half g_xf[3][(size_t)MTOT * DMODEL];     // fp16 query,key,value
__device__ __half g_wf[4][(size_t)DMODEL * DMODEL];   // fp16 Wq,Wk,Wv,Wo
__device__ __half g_qkv[3][(size_t)MTOT * DMODEL];    // fp16 Q,K,V (b,h,s,d); Q pre-scaled
__device__ __half g_ctx[(size_t)MTOT * DMODEL];       // fp16 ctx (b,s,h*d)

// ======================= PTX helpers =======================================
__device__ __forceinline__ uint32_t smem_u32(const void* p) {
    uint32_t a;
    asm("{ .reg .u64 t; cvta.to.shared.u64 t, %1; cvt.u32.u64 %0, t; }"
        : "=r"(a) : "l"(p));
    return a;
}

#define LDSM_X4(r0, r1, r2, r3, addr) \
    asm volatile("ldmatrix.sync.aligned.m8n8.x4.shared.b16 {%0,%1,%2,%3}, [%4];" \
                 : "=r"(r0), "=r"(r1), "=r"(r2), "=r"(r3) : "r"(addr))

#define LDSM_X4_T(r0, r1, r2, r3, addr) \
    asm volatile("ldmatrix.sync.aligned.m8n8.x4.trans.shared.b16 {%0,%1,%2,%3}, [%4];" \
                 : "=r"(r0), "=r"(r1), "=r"(r2), "=r"(r3) : "r"(addr))

#define MMA_FP16(d, a, b0, b1) \
    asm volatile("mma.sync.aligned.m16n8k16.row.col.f32.f16.f16.f32 " \
                 "{%0,%1,%2,%3}, {%4,%5,%6,%7}, {%8,%9}, {%0,%1,%2,%3};" \
                 : "+f"((d)[0]), "+f"((d)[1]), "+f"((d)[2]), "+f"((d)[3]) \
                 : "r"((a)[0]), "r"((a)[1]), "r"((a)[2]), "r"((a)[3]), \
                   "r"(b0), "r"(b1))

#define CPA16(saddr, gptr) \
    asm volatile("cp.async.ca.shared.global [%0], [%1], 16;" \
                 :: "r"(saddr), "l"(gptr))
#define CP_COMMIT() asm volatile("cp.async.commit_group;" ::: "memory")
#define CP_WAIT0()  asm volatile("cp.async.wait_group 0;" ::: "memory")
#define CP_WAIT1()  asm volatile("cp.async.wait_group 1;" ::: "memory")

__device__ __forceinline__ uint32_t pack_f16(float a, float b) {   // low = a
    uint32_t r;
    asm("cvt.rn.f16x2.f32 %0, %1, %2;" : "=r"(r) : "f"(b), "f"(a));
    return r;
}

// ======================= prep: fp32 -> fp16 (one pass) =====================
__global__ void __launch_bounds__(256) prep_f16(
    const float* __restrict__ q, const float* __restrict__ k,
    const float* __restrict__ v,
    const float* __restrict__ Wq, const float* __restrict__ Wk,
    const float* __restrict__ Wv, const float* __restrict__ Wo)
{
    const int z = blockIdx.y;
    const float* srcs[7] = {q, k, v, Wq, Wk, Wv, Wo};
    __half* dsts[7] = {g_xf[0], g_xf[1], g_xf[2],
                       g_wf[0], g_wf[1], g_wf[2], g_wf[3]};
    const int n4 = (z < 3) ? (MTOT * DMODEL / 4) : (DMODEL * DMODEL / 4);
    int i = blockIdx.x * 256 + threadIdx.x;
    if (i < n4) {
        float4 val = ((const float4*)srcs[z])[i];
        ((uint2*)dsts[z])[i] =
            make_uint2(pack_f16(val.x, val.y), pack_f16(val.z, val.w));
    }
}

// ======================= fp16 GEMM: CTA 128x64, warp 32x32, occ 3 ==========
// C = A @ W^T + bias.  A,W fp16 row-major [.,1024].  fp32 accumulate.
// K chunk 32 (two k16 slices), 3-stage cp.async ring.
// MODE 0: fp32 row-major out.  MODE 1: fp16 head-major out, * scale.
#define PITCH_B   48
#define SL_A      6144            // 128 rows * 48B, one k16 slice
#define SL_W      3072            // 64 rows * 48B
#define GW_OFF    12288           // A = 2 slices
#define STAGE_SZ  18432           // A 12288 + W 6144
#define GEMM_SMEM (3 * STAGE_SZ)  // 55296

template <int MODE>
__device__ __forceinline__ void gemm_body_f16(
    const __half* __restrict__ A, const __half* __restrict__ W,
    const float* __restrict__ bias, float* __restrict__ Cf,
    __half* __restrict__ Ch, float scale, char* smem)
{
    const uint32_t sb = smem_u32(smem);
    const int tid  = threadIdx.x;
    const int lane = tid & 31;
    const int wid  = tid >> 5;
    const int wm   = wid & 3;               // 4 m-slabs of 32 rows
    const int wn   = wid >> 2;              // 2 n-slabs of 32 cols
    const int m0   = blockIdx.y * 128;
    const int n0   = blockIdx.x * 64;

    const uint32_t laneOff = (uint32_t)((lane & 15) * PITCH_B + (lane >> 4) * 16);

    float acc[2][4][4];
#pragma unroll
    for (int i = 0; i < 2; ++i)
#pragma unroll
        for (int j = 0; j < 4; ++j)
#pragma unroll
            for (int r = 0; r < 4; ++r) acc[i][j][r] = 0.0f;

    auto issue = [&](int ch) {
        const uint32_t sbuf = sb + (uint32_t)((ch % 3) * STAGE_SZ);
        const int kt = ch * 32;
        // A: 128 rows x 32 halfs = 512 x 16B
#pragma unroll
        for (int i = 0; i < 2; ++i) {
            int slot = i * 256 + tid;
            int row  = slot >> 2;
            int j    = slot & 3;
            uint32_t soff = (uint32_t)((j >> 1) * SL_A + row * PITCH_B + (j & 1) * 16);
            CPA16(sbuf + soff, A + (size_t)(m0 + row) * DMODEL + kt + j * 8);
        }
        // W: 64 rows x 32 halfs = 256 x 16B
        {
            int row = tid >> 2;
            int j   = tid & 3;
            uint32_t soff = (uint32_t)((j >> 1) * SL_W + row * PITCH_B + (j & 1) * 16);
            CPA16(sbuf + GW_OFF + soff, W + (size_t)(n0 + row) * DMODEL + kt + j * 8);
        }
        CP_COMMIT();
    };

    issue(0); issue(1);

#pragma unroll 1
    for (int ch = 0; ch < 32; ++ch) {
        if (ch < 31) CP_WAIT1(); else CP_WAIT0();
        __syncthreads();
        if (ch + 2 < 32) issue(ch + 2);

        const uint32_t bufb = sb + (uint32_t)((ch % 3) * STAGE_SZ);
        const uint32_t aBase = bufb + (uint32_t)(wm * 32) * PITCH_B + laneOff;
        const uint32_t wBase = bufb + GW_OFF + (uint32_t)(wn * 32) * PITCH_B + laneOff;

#pragma unroll
        for (int ks = 0; ks < 2; ++ks) {
            uint32_t ah[2][4], wh[2][4];
#pragma unroll
            for (int mt = 0; mt < 2; ++mt)
                LDSM_X4(ah[mt][0], ah[mt][1], ah[mt][2], ah[mt][3],
                        aBase + (uint32_t)(ks * SL_A) + mt * 16 * PITCH_B);
#pragma unroll
            for (int n2 = 0; n2 < 2; ++n2)
                LDSM_X4(wh[n2][0], wh[n2][1], wh[n2][2], wh[n2][3],
                        wBase + (uint32_t)(ks * SL_W) + n2 * 16 * PITCH_B);
#pragma unroll
            for (int mt = 0; mt < 2; ++mt)
#pragma unroll
                for (int nt = 0; nt < 4; ++nt)
                    MMA_FP16(acc[mt][nt], ah[mt],
                             wh[nt >> 1][nt & 1], wh[nt >> 1][(nt & 1) + 2]);
        }
    }

    const int group = lane >> 2;
    const int tcol  = (lane & 3) * 2;
#pragma unroll
    for (int mt = 0; mt < 2; ++mt) {
#pragma unroll
        for (int nt = 0; nt < 4; ++nt) {
            int row = m0 + wm * 32 + mt * 16 + group;
            int col = n0 + wn * 32 + nt * 8 + tcol;
            float bx = bias[col], by = bias[col + 1];
            float v00 = acc[mt][nt][0] + bx, v01 = acc[mt][nt][1] + by;
            float v10 = acc[mt][nt][2] + bx, v11 = acc[mt][nt][3] + by;
            if (MODE == 0) {
                *(float2*)(Cf + (size_t)row * DMODEL + col) = make_float2(v00, v01);
                *(float2*)(Cf + (size_t)(row + 8) * DMODEL + col) = make_float2(v10, v11);
            } else {
                v00 *= scale; v01 *= scale; v10 *= scale; v11 *= scale;
                int h = col >> 6, d = col & 63;
                int b0_ = row >> 11, s0_ = row & 2047;
                int b1_ = (row + 8) >> 11, s1_ = (row + 8) & 2047;
                *(uint32_t*)(Ch + (((size_t)(b0_ * NHEADS + h) * S_LEN + s0_) * DK) + d)
                    = pack_f16(v00, v01);
                *(uint32_t*)(Ch + (((size_t)(b1_ * NHEADS + h) * S_LEN + s1_) * DK) + d)
                    = pack_f16(v10, v11);
            }
        }
    }
}

__global__ void __launch_bounds__(256, 3) gemm_qkv(
    const float* __restrict__ bq, const float* __restrict__ bk,
    const float* __restrict__ bv)
{
    extern __shared__ __align__(128) char smem[];
    const int z = blockIdx.z;
    const float* bias = (z == 0) ? bq : (z == 1) ? bk : bv;
    const float scale = (z == 0) ? 0.125f : 1.0f;
    gemm_body_f16<1>(g_xf[z], g_wf[z], bias, nullptr, g_qkv[z], scale, smem);
}

__global__ void __launch_bounds__(256, 3) gemm_out(
    const float* __restrict__ bias, float* __restrict__ C)
{
    extern __shared__ __align__(128) char smem[];
    gemm_body_f16<0>(g_ctx, g_wf[3], bias, C, nullptr, 1.0f, smem);
}

// ======================= flash attention, fp16 in/out, 3-stage cp.async ====
#define APITCH    144
#define KV_STAGE  18432           // K 9216 + V 9216
#define AV_OFF    9216
#define QF_OFF    55296           // 3 * KV_STAGE
#define MASK_OFF  73728
#define ATTN_SMEM (MASK_OFF + 2 * 64 * 4)   // 74240

__global__ void __launch_bounds__(256, 2) attn_mma(
    const int* __restrict__ mask)
{
    extern __shared__ __align__(128) char smem[];
    const __half* Q = g_qkv[0];
    const __half* K = g_qkv[1];
    const __half* V = g_qkv[2];
    const uint32_t sb = smem_u32(smem);
    const int tid  = threadIdx.x;
    const int lane = tid & 31;
    const int wid  = tid >> 5;
    const int q0   = blockIdx.x * 128;
    const int h    = blockIdx.y;
    const int b    = blockIdx.z;
    const size_t base = (size_t)(b * NHEADS + h) * S_LEN * DK;

    const uint32_t laneOff = (uint32_t)((lane & 15) * APITCH + (lane >> 4) * 16);

    auto issue_kv = [&](int t) {
        int st = t % 3;
        const uint32_t sp = sb + (uint32_t)(st * KV_STAGE);
        const int k0 = t * 64;
#pragma unroll
        for (int i = 0; i < 2; ++i) {
            int slot = i * 256 + tid;
            int row  = slot >> 3;
            int g    = slot & 7;
            uint32_t soff = (uint32_t)(row * APITCH + g * 16);
            size_t goff = base + (size_t)(k0 + row) * DK + g * 8;
            CPA16(sp + soff,          K + goff);
            CPA16(sp + AV_OFF + soff, V + goff);
        }
        CP_COMMIT();
    };

#pragma unroll
    for (int i = 0; i < 4; ++i) {
        int slot = i * 256 + tid;
        int row  = slot >> 3;
        int g    = slot & 7;
        uint4 v = *(const uint4*)(Q + base + (size_t)(q0 + row) * DK + g * 8);
        *(uint4*)(smem + QF_OFF + row * APITCH + g * 16) = v;
    }
    issue_kv(0);
    issue_kv(1);
    __syncthreads();

    uint32_t qf[4][4];
    {
        const uint32_t qB = sb + QF_OFF + (uint32_t)(wid * 16) * APITCH + laneOff;
#pragma unroll
        for (int s = 0; s < 4; ++s)
            LDSM_X4(qf[s][0], qf[s][1], qf[s][2], qf[s][3], qB + s * 32);
    }

    float o[8][4];
#pragma unroll
    for (int dt = 0; dt < 8; ++dt)
#pragma unroll
        for (int r = 0; r < 4; ++r) o[dt][r] = 0.0f;
    float mi0 = -1.0e30f, mi1 = -1.0e30f, li0 = 0.0f, li1 = 0.0f;

#pragma unroll 1
    for (int t = 0; t < 32; ++t) {
        if (tid < 64)
            ((int*)(smem + MASK_OFF))[(t & 1) * 64 + tid] = mask[b * S_LEN + t * 64 + tid];
        if (t < 31) CP_WAIT1(); else CP_WAIT0();
        __syncthreads();
        if (t + 2 < 32) issue_kv(t + 2);

        const uint32_t kB = sb + (uint32_t)((t % 3) * KV_STAGE) + laneOff;

        float s_[8][4];
#pragma unroll
        for (int nt = 0; nt < 8; ++nt)
#pragma unroll
            for (int r = 0; r < 4; ++r) s_[nt][r] = 0.0f;
#pragma unroll
        for (int st = 0; st < 4; ++st) {
#pragma unroll
            for (int g2 = 0; g2 < 4; ++g2) {
                uint32_t kf[4];
                LDSM_X4(kf[0], kf[1], kf[2], kf[3],
                        kB + g2 * (16 * APITCH) + st * 32);
                MMA_FP16(s_[2 * g2],     qf[st], kf[0], kf[2]);
                MMA_FP16(s_[2 * g2 + 1], qf[st], kf[1], kf[3]);
            }
        }

        const int* mbuf = (const int*)(smem + MASK_OFF) + (t & 1) * 64;
#pragma unroll
        for (int nt = 0; nt < 8; ++nt) {
            int2 mv = *(const int2*)&mbuf[nt * 8 + (lane & 3) * 2];
            if (mv.x == 0) { s_[nt][0] = -1.0e9f; s_[nt][2] = -1.0e9f; }
            if (mv.y == 0) { s_[nt][1] = -1.0e9f; s_[nt][3] = -1.0e9f; }
        }

        float mx0 = -1.0e30f, mx1 = -1.0e30f;
#pragma unroll
        for (int nt = 0; nt < 8; ++nt) {
            mx0 = fmaxf(mx0, fmaxf(s_[nt][0], s_[nt][1]));
            mx1 = fmaxf(mx1, fmaxf(s_[nt][2], s_[nt][3]));
        }
        mx0 = fmaxf(mx0, __shfl_xor_sync(0xffffffffu, mx0, 1));
        mx0 = fmaxf(mx0, __shfl_xor_sync(0xffffffffu, mx0, 2));
        mx1 = fmaxf(mx1, __shfl_xor_sync(0xffffffffu, mx1, 1));
        mx1 = fmaxf(mx1, __shfl_xor_sync(0xffffffffu, mx1, 2));
        const float mn0 = fmaxf(mi0, mx0), mn1 = fmaxf(mi1, mx1);
        const float a0 = __expf(mi0 - mn0), a1 = __expf(mi1 - mn1);
        mi0 = mn0; mi1 = mn1;

        float sum0 = 0.0f, sum1 = 0.0f;
#pragma unroll
        for (int nt = 0; nt < 8; ++nt) {
            s_[nt][0] = __expf(s_[nt][0] - mn0);
            s_[nt][1] = __expf(s_[nt][1] - mn0);
            s_[nt][2] = __expf(s_[nt][2] - mn1);
            s_[nt][3] = __expf(s_[nt][3] - mn1);
            sum0 += s_[nt][0] + s_[nt][1];
            sum1 += s_[nt][2] + s_[nt][3];
        }
        sum0 += __shfl_xor_sync(0xffffffffu, sum0, 1);
        sum0 += __shfl_xor_sync(0xffffffffu, sum0, 2);
        sum1 += __shfl_xor_sync(0xffffffffu, sum1, 1);
        sum1 += __shfl_xor_sync(0xffffffffu, sum1, 2);
        li0 = li0 * a0 + sum0;
        li1 = li1 * a1 + sum1;

#pragma unroll
        for (int dt = 0; dt < 8; ++dt) {
            o[dt][0] *= a0; o[dt][1] *= a0;
            o[dt][2] *= a1; o[dt][3] *= a1;
        }

        const uint32_t vB = sb + (uint32_t)((t % 3) * KV_STAGE) + AV_OFF + laneOff;
#pragma unroll
        for (int st = 0; st < 4; ++st) {
            uint32_t pf[4];
            pf[0] = pack_f16(s_[2 * st][0],     s_[2 * st][1]);
            pf[1] = pack_f16(s_[2 * st][2],     s_[2 * st][3]);
            pf[2] = pack_f16(s_[2 * st + 1][0], s_[2 * st + 1][1]);
            pf[3] = pack_f16(s_[2 * st + 1][2], s_[2 * st + 1][3]);
#pragma unroll
            for (int j = 0; j < 4; ++j) {
                uint32_t vf[4];
                LDSM_X4_T(vf[0], vf[1], vf[2], vf[3],
                          vB + st * (16 * APITCH) + j * 32);
                MMA_FP16(o[2 * j],     pf, vf[0], vf[1]);
                MMA_FP16(o[2 * j + 1], pf, vf[2], vf[3]);
            }
        }
    }

    const int g  = lane >> 2;
    const int t2 = (lane & 3) * 2;
    const int row0 = q0 + wid * 16 + g;
    const int row1 = row0 + 8;
    const float inv0 = 1.0f / li0, inv1 = 1.0f / li1;
#pragma unroll
    for (int dt = 0; dt < 8; ++dt) {
        int col = h * DK + dt * 8 + t2;
        *(uint32_t*)(g_ctx + (size_t)(b * S_LEN + row0) * DMODEL + col) =
            pack_f16(o[dt][0] * inv0, o[dt][1] * inv0);
        *(uint32_t*)(g_ctx + (size_t)(b * S_LEN + row1) * DMODEL + col) =
            pack_f16(o[dt][2] * inv1, o[dt][3] * inv1);
    }
}

// ---------------------------------------------------------------------------
extern "C" void kernel_launch(void* const* d_in, const int* in_sizes, int n_in,
                              void* d_out, int out_size)
{
    const float* query = (const float*)d_in[0];
    const float* key   = (const float*)d_in[1];
    const float* value = (const float*)d_in[2];
    const int*   mask  = (const int*)d_in[3];
    const float* Wq = (const float*)d_in[4];
    const float* bq = (const float*)d_in[5];
    const float* Wk = (const float*)d_in[6];
    const float* bk = (const float*)d_in[7];
    const float* Wv = (const float*)d_in[8];
    const float* bv = (const float*)d_in[9];
    const float* Wo = (const float*)d_in[10];
    const float* bo = (const float*)d_in[11];
    float* out = (float*)d_out;

    cudaFuncSetAttribute(gemm_qkv, cudaFuncAttributeMaxDynamicSharedMemorySize, GEMM_SMEM);
    cudaFuncSetAttribute(gemm_out, cudaFuncAttributeMaxDynamicSharedMemorySize, GEMM_SMEM);
    cudaFuncSetAttribute(attn_mma, cudaFuncAttributeMaxDynamicSharedMemorySize, ATTN_SMEM);

    dim3 pg((MTOT * DMODEL / 4 + 255) / 256, 7);     // (4096, 7)
    prep_f16<<<pg, 256>>>(query, key, value, Wq, Wk, Wv, Wo);

    dim3 gq(DMODEL / 64, MTOT / 128, 3);             // (16, 32, 3) = 1536 CTAs
    gemm_qkv<<<gq, 256, GEMM_SMEM>>>(bq, bk, bv);

    dim3 ag(S_LEN / 128, NHEADS, BATCH);             // (16, 16, 2) = 512 CTAs
    attn_mma<<<ag, 256, ATTN_SMEM>>>(mask);

    dim3 gg(DMODEL / 64, MTOT / 128);                // (16, 32) = 512 CTAs
    gemm_out<<<gg, 256, GEMM_SMEM>>>(bo, out);
}

// round 16
// speedup vs baseline: 1.0551x; 1.0551x over previous
#include <cuda_runtime.h>
#include <cuda_fp16.h>
#include <cstdint>

#define S_LEN   2048
#define BATCH   2
#define DMODEL  1024
#define NHEADS  16
#define DK      64
#define MTOT    (BATCH * S_LEN)   // 4096

// ---------------- scratch (static device globals; no dynamic allocation) ----
__device__ __half g_xf[3][(size_t)MTOT * DMODEL];     // fp16 query,key,value
__device__ __half g_wf[4][(size_t)DMODEL * DMODEL];   // fp16 Wq,Wk,Wv,Wo
__device__ __half g_qkv[3][(size_t)MTOT * DMODEL];    // fp16 Q,K,V (b,h,s,d); Q pre-scaled
__device__ __half g_ctx[(size_t)MTOT * DMODEL];       // fp16 ctx (b,s,h*d)

// ======================= PTX helpers =======================================
__device__ __forceinline__ uint32_t smem_u32(const void* p) {
    uint32_t a;
    asm("{ .reg .u64 t; cvta.to.shared.u64 t, %1; cvt.u32.u64 %0, t; }"
        : "=r"(a) : "l"(p));
    return a;
}

#define LDSM_X4(r0, r1, r2, r3, addr) \
    asm volatile("ldmatrix.sync.aligned.m8n8.x4.shared.b16 {%0,%1,%2,%3}, [%4];" \
                 : "=r"(r0), "=r"(r1), "=r"(r2), "=r"(r3) : "r"(addr))

#define LDSM_X4_T(r0, r1, r2, r3, addr) \
    asm volatile("ldmatrix.sync.aligned.m8n8.x4.trans.shared.b16 {%0,%1,%2,%3}, [%4];" \
                 : "=r"(r0), "=r"(r1), "=r"(r2), "=r"(r3) : "r"(addr))

#define MMA_FP16(d, a, b0, b1) \
    asm volatile("mma.sync.aligned.m16n8k16.row.col.f32.f16.f16.f32 " \
                 "{%0,%1,%2,%3}, {%4,%5,%6,%7}, {%8,%9}, {%0,%1,%2,%3};" \
                 : "+f"((d)[0]), "+f"((d)[1]), "+f"((d)[2]), "+f"((d)[3]) \
                 : "r"((a)[0]), "r"((a)[1]), "r"((a)[2]), "r"((a)[3]), \
                   "r"(b0), "r"(b1))

#define CPA16(saddr, gptr) \
    asm volatile("cp.async.ca.shared.global [%0], [%1], 16;" \
                 :: "r"(saddr), "l"(gptr))
#define CP_COMMIT() asm volatile("cp.async.commit_group;" ::: "memory")
#define CP_WAIT0()  asm volatile("cp.async.wait_group 0;" ::: "memory")
#define CP_WAIT1()  asm volatile("cp.async.wait_group 1;" ::: "memory")
#define CP_WAIT2()  asm volatile("cp.async.wait_group 2;" ::: "memory")

__device__ __forceinline__ uint32_t pack_f16(float a, float b) {   // low = a
    uint32_t r;
    asm("cvt.rn.f16x2.f32 %0, %1, %2;" : "=r"(r) : "f"(b), "f"(a));
    return r;
}

// ======================= prep: fp32 -> fp16 (one pass) =====================
__global__ void __launch_bounds__(256) prep_f16(
    const float* __restrict__ q, const float* __restrict__ k,
    const float* __restrict__ v,
    const float* __restrict__ Wq, const float* __restrict__ Wk,
    const float* __restrict__ Wv, const float* __restrict__ Wo)
{
    const int z = blockIdx.y;
    const float* srcs[7] = {q, k, v, Wq, Wk, Wv, Wo};
    __half* dsts[7] = {g_xf[0], g_xf[1], g_xf[2],
                       g_wf[0], g_wf[1], g_wf[2], g_wf[3]};
    const int n4 = (z < 3) ? (MTOT * DMODEL / 4) : (DMODEL * DMODEL / 4);
    int i = blockIdx.x * 256 + threadIdx.x;
    if (i < n4) {
        float4 val = ((const float4*)srcs[z])[i];
        ((uint2*)dsts[z])[i] =
            make_uint2(pack_f16(val.x, val.y), pack_f16(val.z, val.w));
    }
}

// ======================= fp16 GEMM, 4-stage cp.async (R12, proven) =========
// C = A @ W^T + bias.  A,W fp16 row-major [.,1024].  fp32 accumulate.
// MODE 0: fp32 row-major out.  MODE 1: fp16 head-major out, * scale.
#define PITCH_B   48
#define SL_SZ     6144
#define STAGE_SZ  24576           // A 12288 + W 12288
#define GW_OFF    12288
#define GEMM_SMEM (4 * STAGE_SZ)  // 98304

template <int MODE>
__device__ __forceinline__ void gemm_body_f16(
    const __half* __restrict__ A, const __half* __restrict__ W,
    const float* __restrict__ bias, float* __restrict__ Cf,
    __half* __restrict__ Ch, float scale, char* smem)
{
    const uint32_t sb = smem_u32(smem);
    const int tid  = threadIdx.x;
    const int lane = tid & 31;
    const int wid  = tid >> 5;
    const int wm   = wid >> 2;
    const int wn   = wid & 3;
    const int m0   = blockIdx.y * 128;
    const int n0   = blockIdx.x * 128;

    const uint32_t laneOff = (uint32_t)((lane & 15) * PITCH_B + (lane >> 4) * 16);

    float acc[4][4][4];
#pragma unroll
    for (int i = 0; i < 4; ++i)
#pragma unroll
        for (int j = 0; j < 4; ++j)
#pragma unroll
            for (int r = 0; r < 4; ++r) acc[i][j][r] = 0.0f;

    auto issue = [&](int ch) {
        const uint32_t sbuf = sb + (uint32_t)((ch & 3) * STAGE_SZ);
        const int kt = ch * 32;
#pragma unroll
        for (int i = 0; i < 2; ++i) {
            int slot = i * 256 + tid;           // 0..511
            int row  = slot >> 2;               // 0..127
            int j    = slot & 3;                // 8-half group
            uint32_t soff = (uint32_t)((j >> 1) * SL_SZ + row * PITCH_B + (j & 1) * 16);
            CPA16(sbuf + soff,          A + (size_t)(m0 + row) * DMODEL + kt + j * 8);
            CPA16(sbuf + GW_OFF + soff, W + (size_t)(n0 + row) * DMODEL + kt + j * 8);
        }
        CP_COMMIT();
    };

    issue(0); issue(1); issue(2);

#pragma unroll 1
    for (int ch = 0; ch < 32; ++ch) {
        if (ch < 30)      CP_WAIT2();
        else if (ch == 30) CP_WAIT1();
        else               CP_WAIT0();
        __syncthreads();
        if (ch + 3 < 32) issue(ch + 3);

        const uint32_t bufb = sb + (uint32_t)((ch & 3) * STAGE_SZ);
        const uint32_t aBase = bufb + (uint32_t)(wm * 64) * PITCH_B + laneOff;
        const uint32_t wBase = bufb + GW_OFF + (uint32_t)(wn * 32) * PITCH_B + laneOff;

#pragma unroll
        for (int ks = 0; ks < 2; ++ks) {
            const uint32_t so = (uint32_t)ks * SL_SZ;
            uint32_t ah[4][4], wh[2][4];
#pragma unroll
            for (int mt = 0; mt < 4; ++mt)
                LDSM_X4(ah[mt][0], ah[mt][1], ah[mt][2], ah[mt][3],
                        aBase + so + mt * 16 * PITCH_B);
#pragma unroll
            for (int n2 = 0; n2 < 2; ++n2)
                LDSM_X4(wh[n2][0], wh[n2][1], wh[n2][2], wh[n2][3],
                        wBase + so + n2 * 16 * PITCH_B);
#pragma unroll
            for (int mt = 0; mt < 4; ++mt)
#pragma unroll
                for (int nt = 0; nt < 4; ++nt)
                    MMA_FP16(acc[mt][nt], ah[mt],
                             wh[nt >> 1][nt & 1], wh[nt >> 1][(nt & 1) + 2]);
        }
    }

    const int group = lane >> 2;
    const int tcol  = (lane & 3) * 2;
#pragma unroll
    for (int mt = 0; mt < 4; ++mt) {
#pragma unroll
        for (int nt = 0; nt < 4; ++nt) {
            int row = m0 + wm * 64 + mt * 16 + group;
            int col = n0 + wn * 32 + nt * 8 + tcol;
            float bx = bias[col], by = bias[col + 1];
            float v00 = acc[mt][nt][0] + bx, v01 = acc[mt][nt][1] + by;
            float v10 = acc[mt][nt][2] + bx, v11 = acc[mt][nt][3] + by;
            if (MODE == 0) {
                *(float2*)(Cf + (size_t)row * DMODEL + col) = make_float2(v00, v01);
                *(float2*)(Cf + (size_t)(row + 8) * DMODEL + col) = make_float2(v10, v11);
            } else {
                v00 *= scale; v01 *= scale; v10 *= scale; v11 *= scale;
                int h = col >> 6, d = col & 63;
                int b0_ = row >> 11, s0_ = row & 2047;
                int b1_ = (row + 8) >> 11, s1_ = (row + 8) & 2047;
                *(uint32_t*)(Ch + (((size_t)(b0_ * NHEADS + h) * S_LEN + s0_) * DK) + d)
                    = pack_f16(v00, v01);
                *(uint32_t*)(Ch + (((size_t)(b1_ * NHEADS + h) * S_LEN + s1_) * DK) + d)
                    = pack_f16(v10, v11);
            }
        }
    }
}

__global__ void __launch_bounds__(256, 2) gemm_qkv(
    const float* __restrict__ bq, const float* __restrict__ bk,
    const float* __restrict__ bv)
{
    extern __shared__ __align__(128) char smem[];
    const int z = blockIdx.z;
    const float* bias = (z == 0) ? bq : (z == 1) ? bk : bv;
    const float scale = (z == 0) ? 0.125f : 1.0f;
    gemm_body_f16<1>(g_xf[z], g_wf[z], bias, nullptr, g_qkv[z], scale, smem);
}

__global__ void __launch_bounds__(256, 2) gemm_out(
    const float* __restrict__ bias, float* __restrict__ C)
{
    extern __shared__ __align__(128) char smem[];
    gemm_body_f16<0>(g_ctx, g_wf[3], bias, C, nullptr, 1.0f, smem);
}

// ======================= flash attention, fp16 in/out, 4-stage cp.async ====
#define APITCH    144
#define KV_STAGE  18432           // K 9216 + V 9216
#define AV_OFF    9216
#define QF_OFF    73728           // 4 * KV_STAGE
#define MASK_OFF  92160
#define ATTN_SMEM (MASK_OFF + 2 * 64 * 4)   // 92672

__global__ void __launch_bounds__(256, 2) attn_mma(
    const int* __restrict__ mask)
{
    extern __shared__ __align__(128) char smem[];
    const __half* Q = g_qkv[0];
    const __half* K = g_qkv[1];
    const __half* V = g_qkv[2];
    const uint32_t sb = smem_u32(smem);
    const int tid  = threadIdx.x;
    const int lane = tid & 31;
    const int wid  = tid >> 5;
    const int q0   = blockIdx.x * 128;
    const int h    = blockIdx.y;
    const int b    = blockIdx.z;
    const size_t base = (size_t)(b * NHEADS + h) * S_LEN * DK;

    const uint32_t laneOff = (uint32_t)((lane & 15) * APITCH + (lane >> 4) * 16);

    auto issue_kv = [&](int t) {
        const uint32_t sp = sb + (uint32_t)((t & 3) * KV_STAGE);
        const int k0 = t * 64;
#pragma unroll
        for (int i = 0; i < 2; ++i) {
            int slot = i * 256 + tid;
            int row  = slot >> 3;
            int g    = slot & 7;
            uint32_t soff = (uint32_t)(row * APITCH + g * 16);
            size_t goff = base + (size_t)(k0 + row) * DK + g * 8;
            CPA16(sp + soff,          K + goff);
            CPA16(sp + AV_OFF + soff, V + goff);
        }
        CP_COMMIT();
    };

    // stage Q (fp16, already scaled) + first three K/V tiles
#pragma unroll
    for (int i = 0; i < 4; ++i) {
        int slot = i * 256 + tid;
        int row  = slot >> 3;
        int g    = slot & 7;
        uint4 v = *(const uint4*)(Q + base + (size_t)(q0 + row) * DK + g * 8);
        *(uint4*)(smem + QF_OFF + row * APITCH + g * 16) = v;
    }
    issue_kv(0);
    issue_kv(1);
    issue_kv(2);
    __syncthreads();

    uint32_t qf[4][4];
    {
        const uint32_t qB = sb + QF_OFF + (uint32_t)(wid * 16) * APITCH + laneOff;
#pragma unroll
        for (int s = 0; s < 4; ++s)
            LDSM_X4(qf[s][0], qf[s][1], qf[s][2], qf[s][3], qB + s * 32);
    }

    float o[8][4];
#pragma unroll
    for (int dt = 0; dt < 8; ++dt)
#pragma unroll
        for (int r = 0; r < 4; ++r) o[dt][r] = 0.0f;
    float mi0 = -1.0e30f, mi1 = -1.0e30f, li0 = 0.0f, li1 = 0.0f;

#pragma unroll 1
    for (int t = 0; t < 32; ++t) {
        if (tid < 64)
            ((int*)(smem + MASK_OFF))[(t & 1) * 64 + tid] = mask[b * S_LEN + t * 64 + tid];
        if (t < 30)      CP_WAIT2();        // group t complete (own)
        else if (t == 30) CP_WAIT1();
        else              CP_WAIT0();
        __syncthreads();                     // everyone's group t complete
        if (t + 3 < 32) issue_kv(t + 3);     // writes stage (t-1)&3, freed by barrier

        const uint32_t kB = sb + (uint32_t)((t & 3) * KV_STAGE) + laneOff;

        // ---- S = Q K^T ----
        float s_[8][4];
#pragma unroll
        for (int nt = 0; nt < 8; ++nt)
#pragma unroll
            for (int r = 0; r < 4; ++r) s_[nt][r] = 0.0f;
#pragma unroll
        for (int st = 0; st < 4; ++st) {
#pragma unroll
            for (int g2 = 0; g2 < 4; ++g2) {
                uint32_t kf[4];
                LDSM_X4(kf[0], kf[1], kf[2], kf[3],
                        kB + g2 * (16 * APITCH) + st * 32);
                MMA_FP16(s_[2 * g2],     qf[st], kf[0], kf[2]);
                MMA_FP16(s_[2 * g2 + 1], qf[st], kf[1], kf[3]);
            }
        }

        // ---- mask ----
        const int* mbuf = (const int*)(smem + MASK_OFF) + (t & 1) * 64;
#pragma unroll
        for (int nt = 0; nt < 8; ++nt) {
            int2 mv = *(const int2*)&mbuf[nt * 8 + (lane & 3) * 2];
            if (mv.x == 0) { s_[nt][0] = -1.0e9f; s_[nt][2] = -1.0e9f; }
            if (mv.y == 0) { s_[nt][1] = -1.0e9f; s_[nt][3] = -1.0e9f; }
        }

        // ---- online softmax ----
        float mx0 = -1.0e30f, mx1 = -1.0e30f;
#pragma unroll
        for (int nt = 0; nt < 8; ++nt) {
            mx0 = fmaxf(mx0, fmaxf(s_[nt][0], s_[nt][1]));
            mx1 = fmaxf(mx1, fmaxf(s_[nt][2], s_[nt][3]));
        }
        mx0 = fmaxf(mx0, __shfl_xor_sync(0xffffffffu, mx0, 1));
        mx0 = fmaxf(mx0, __shfl_xor_sync(0xffffffffu, mx0, 2));
        mx1 = fmaxf(mx1, __shfl_xor_sync(0xffffffffu, mx1, 1));
        mx1 = fmaxf(mx1, __shfl_xor_sync(0xffffffffu, mx1, 2));
        const float mn0 = fmaxf(mi0, mx0), mn1 = fmaxf(mi1, mx1);
        const float a0 = __expf(mi0 - mn0), a1 = __expf(mi1 - mn1);
        mi0 = mn0; mi1 = mn1;

        float sum0 = 0.0f, sum1 = 0.0f;
#pragma unroll
        for (int nt = 0; nt < 8; ++nt) {
            s_[nt][0] = __expf(s_[nt][0] - mn0);
            s_[nt][1] = __expf(s_[nt][1] - mn0);
            s_[nt][2] = __expf(s_[nt][2] - mn1);
            s_[nt][3] = __expf(s_[nt][3] - mn1);
            sum0 += s_[nt][0] + s_[nt][1];
            sum1 += s_[nt][2] + s_[nt][3];
        }
        sum0 += __shfl_xor_sync(0xffffffffu, sum0, 1);
        sum0 += __shfl_xor_sync(0xffffffffu, sum0, 2);
        sum1 += __shfl_xor_sync(0xffffffffu, sum1, 1);
        sum1 += __shfl_xor_sync(0xffffffffu, sum1, 2);
        li0 = li0 * a0 + sum0;
        li1 = li1 * a1 + sum1;

#pragma unroll
        for (int dt = 0; dt < 8; ++dt) {
            o[dt][0] *= a0; o[dt][1] *= a0;
            o[dt][2] *= a1; o[dt][3] *= a1;
        }

        // ---- O += P V ----
        const uint32_t vB = sb + (uint32_t)((t & 3) * KV_STAGE) + AV_OFF + laneOff;
#pragma unroll
        for (int st = 0; st < 4; ++st) {
            uint32_t pf[4];
            pf[0] = pack_f16(s_[2 * st][0],     s_[2 * st][1]);
            pf[1] = pack_f16(s_[2 * st][2],     s_[2 * st][3]);
            pf[2] = pack_f16(s_[2 * st + 1][0], s_[2 * st + 1][1]);
            pf[3] = pack_f16(s_[2 * st + 1][2], s_[2 * st + 1][3]);
#pragma unroll
            for (int j = 0; j < 4; ++j) {
                uint32_t vf[4];
                LDSM_X4_T(vf[0], vf[1], vf[2], vf[3],
                          vB + st * (16 * APITCH) + j * 32);
                MMA_FP16(o[2 * j],     pf, vf[0], vf[1]);
                MMA_FP16(o[2 * j + 1], pf, vf[2], vf[3]);
            }
        }
    }

    // ---- epilogue: normalize, write ctx fp16 (b, s, h*64+d) ----
    const int g  = lane >> 2;
    const int t2 = (lane & 3) * 2;
    const int row0 = q0 + wid * 16 + g;
    const int row1 = row0 + 8;
    const float inv0 = 1.0f / li0, inv1 = 1.0f / li1;
#pragma unroll
    for (int dt = 0; dt < 8; ++dt) {
        int col = h * DK + dt * 8 + t2;
        *(uint32_t*)(g_ctx + (size_t)(b * S_LEN + row0) * DMODEL + col) =
            pack_f16(o[dt][0] * inv0, o[dt][1] * inv0);
        *(uint32_t*)(g_ctx + (size_t)(b * S_LEN + row1) * DMODEL + col) =
            pack_f16(o[dt][2] * inv1, o[dt][3] * inv1);
    }
}

// ---------------------------------------------------------------------------
extern "C" void kernel_launch(void* const* d_in, const int* in_sizes, int n_in,
                              void* d_out, int out_size)
{
    const float* query = (const float*)d_in[0];
    const float* key   = (const float*)d_in[1];
    const float* value = (const float*)d_in[2];
    const int*   mask  = (const int*)d_in[3];
    const float* Wq = (const float*)d_in[4];
    const float* bq = (const float*)d_in[5];
    const float* Wk = (const float*)d_in[6];
    const float* bk = (const float*)d_in[7];
    const float* Wv = (const float*)d_in[8];
    const float* bv = (const float*)d_in[9];
    const float* Wo = (const float*)d_in[10];
    const float* bo = (const float*)d_in[11];
    float* out = (float*)d_out;

    cudaFuncSetAttribute(gemm_qkv, cudaFuncAttributeMaxDynamicSharedMemorySize, GEMM_SMEM);
    cudaFuncSetAttribute(gemm_out, cudaFuncAttributeMaxDynamicSharedMemorySize, GEMM_SMEM);
    cudaFuncSetAttribute(attn_mma, cudaFuncAttributeMaxDynamicSharedMemorySize, ATTN_SMEM);

    dim3 pg((MTOT * DMODEL / 4 + 255) / 256, 7);     // (4096, 7)
    prep_f16<<<pg, 256>>>(query, key, value, Wq, Wk, Wv, Wo);

    dim3 gq(DMODEL / 128, MTOT / 128, 3);            // (8, 32, 3) = 768 CTAs
    gemm_qkv<<<gq, 256, GEMM_SMEM>>>(bq, bk, bv);

    dim3 ag(S_LEN / 128, NHEADS, BATCH);             // (16, 16, 2) = 512 CTAs
    attn_mma<<<ag, 256, ATTN_SMEM>>>(mask);

    dim3 gg(DMODEL / 128, MTOT / 128);               // (8, 32) = 256 CTAs
    gemm_out<<<gg, 256, GEMM_SMEM>>>(bo, out);
}

// round 17
// speedup vs baseline: 1.0925x; 1.0354x over previous
#include <cuda_runtime.h>
#include <cuda_fp16.h>
#include <cstdint>

#define S_LEN   2048
#define BATCH   2
#define DMODEL  1024
#define NHEADS  16
#define DK      64
#define MTOT    (BATCH * S_LEN)   // 4096

// ---------------- scratch (static device globals; no dynamic allocation) ----
__device__ __half g_xf[3][(size_t)MTOT * DMODEL];     // fp16 query,key,value
__device__ __half g_wf[4][(size_t)DMODEL * DMODEL];   // fp16 Wq,Wk,Wv,Wo
__device__ __half g_qkv[3][(size_t)MTOT * DMODEL];    // fp16 Q,K,V (b,h,s,d); Q pre-scaled
__device__ __half g_ctx[(size_t)MTOT * DMODEL];       // fp16 ctx (b,s,h*d)

// ======================= PTX helpers =======================================
__device__ __forceinline__ uint32_t smem_u32(const void* p) {
    uint32_t a;
    asm("{ .reg .u64 t; cvta.to.shared.u64 t, %1; cvt.u32.u64 %0, t; }"
        : "=r"(a) : "l"(p));
    return a;
}

#define LDSM_X4(r0, r1, r2, r3, addr) \
    asm volatile("ldmatrix.sync.aligned.m8n8.x4.shared.b16 {%0,%1,%2,%3}, [%4];" \
                 : "=r"(r0), "=r"(r1), "=r"(r2), "=r"(r3) : "r"(addr))

#define LDSM_X4_T(r0, r1, r2, r3, addr) \
    asm volatile("ldmatrix.sync.aligned.m8n8.x4.trans.shared.b16 {%0,%1,%2,%3}, [%4];" \
                 : "=r"(r0), "=r"(r1), "=r"(r2), "=r"(r3) : "r"(addr))

#define MMA_FP16(d, a, b0, b1) \
    asm volatile("mma.sync.aligned.m16n8k16.row.col.f32.f16.f16.f32 " \
                 "{%0,%1,%2,%3}, {%4,%5,%6,%7}, {%8,%9}, {%0,%1,%2,%3};" \
                 : "+f"((d)[0]), "+f"((d)[1]), "+f"((d)[2]), "+f"((d)[3]) \
                 : "r"((a)[0]), "r"((a)[1]), "r"((a)[2]), "r"((a)[3]), \
                   "r"(b0), "r"(b1))

#define CPA16(saddr, gptr) \
    asm volatile("cp.async.ca.shared.global [%0], [%1], 16;" \
                 :: "r"(saddr), "l"(gptr))
#define CP_COMMIT() asm volatile("cp.async.commit_group;" ::: "memory")
#define CP_WAIT0()  asm volatile("cp.async.wait_group 0;" ::: "memory")
#define CP_WAIT1()  asm volatile("cp.async.wait_group 1;" ::: "memory")
#define CP_WAIT2()  asm volatile("cp.async.wait_group 2;" ::: "memory")

__device__ __forceinline__ uint32_t pack_f16(float a, float b) {   // low = a
    uint32_t r;
    asm("cvt.rn.f16x2.f32 %0, %1, %2;" : "=r"(r) : "f"(b), "f"(a));
    return r;
}

// ======================= prep: fp32 -> fp16 (one pass) =====================
__global__ void __launch_bounds__(256) prep_f16(
    const float* __restrict__ q, const float* __restrict__ k,
    const float* __restrict__ v,
    const float* __restrict__ Wq, const float* __restrict__ Wk,
    const float* __restrict__ Wv, const float* __restrict__ Wo)
{
    const int z = blockIdx.y;
    const float* srcs[7] = {q, k, v, Wq, Wk, Wv, Wo};
    __half* dsts[7] = {g_xf[0], g_xf[1], g_xf[2],
                       g_wf[0], g_wf[1], g_wf[2], g_wf[3]};
    const int n4 = (z < 3) ? (MTOT * DMODEL / 4) : (DMODEL * DMODEL / 4);
    int i = blockIdx.x * 256 + threadIdx.x;
    if (i < n4) {
        float4 val = ((const float4*)srcs[z])[i];
        ((uint2*)dsts[z])[i] =
            make_uint2(pack_f16(val.x, val.y), pack_f16(val.z, val.w));
    }
}

// ======================= fp16 GEMM, 4-stage cp.async (R12, proven) =========
#define PITCH_B   48
#define SL_SZ     6144
#define STAGE_SZ  24576           // A 12288 + W 12288
#define GW_OFF    12288
#define GEMM_SMEM (4 * STAGE_SZ)  // 98304

template <int MODE>
__device__ __forceinline__ void gemm_body_f16(
    const __half* __restrict__ A, const __half* __restrict__ W,
    const float* __restrict__ bias, float* __restrict__ Cf,
    __half* __restrict__ Ch, float scale, char* smem)
{
    const uint32_t sb = smem_u32(smem);
    const int tid  = threadIdx.x;
    const int lane = tid & 31;
    const int wid  = tid >> 5;
    const int wm   = wid >> 2;
    const int wn   = wid & 3;
    const int m0   = blockIdx.y * 128;
    const int n0   = blockIdx.x * 128;

    const uint32_t laneOff = (uint32_t)((lane & 15) * PITCH_B + (lane >> 4) * 16);

    float acc[4][4][4];
#pragma unroll
    for (int i = 0; i < 4; ++i)
#pragma unroll
        for (int j = 0; j < 4; ++j)
#pragma unroll
            for (int r = 0; r < 4; ++r) acc[i][j][r] = 0.0f;

    auto issue = [&](int ch) {
        const uint32_t sbuf = sb + (uint32_t)((ch & 3) * STAGE_SZ);
        const int kt = ch * 32;
#pragma unroll
        for (int i = 0; i < 2; ++i) {
            int slot = i * 256 + tid;           // 0..511
            int row  = slot >> 2;               // 0..127
            int j    = slot & 3;                // 8-half group
            uint32_t soff = (uint32_t)((j >> 1) * SL_SZ + row * PITCH_B + (j & 1) * 16);
            CPA16(sbuf + soff,          A + (size_t)(m0 + row) * DMODEL + kt + j * 8);
            CPA16(sbuf + GW_OFF + soff, W + (size_t)(n0 + row) * DMODEL + kt + j * 8);
        }
        CP_COMMIT();
    };

    issue(0); issue(1); issue(2);

#pragma unroll 1
    for (int ch = 0; ch < 32; ++ch) {
        if (ch < 30)      CP_WAIT2();
        else if (ch == 30) CP_WAIT1();
        else               CP_WAIT0();
        __syncthreads();
        if (ch + 3 < 32) issue(ch + 3);

        const uint32_t bufb = sb + (uint32_t)((ch & 3) * STAGE_SZ);
        const uint32_t aBase = bufb + (uint32_t)(wm * 64) * PITCH_B + laneOff;
        const uint32_t wBase = bufb + GW_OFF + (uint32_t)(wn * 32) * PITCH_B + laneOff;

#pragma unroll
        for (int ks = 0; ks < 2; ++ks) {
            const uint32_t so = (uint32_t)ks * SL_SZ;
            uint32_t ah[4][4], wh[2][4];
#pragma unroll
            for (int mt = 0; mt < 4; ++mt)
                LDSM_X4(ah[mt][0], ah[mt][1], ah[mt][2], ah[mt][3],
                        aBase + so + mt * 16 * PITCH_B);
#pragma unroll
            for (int n2 = 0; n2 < 2; ++n2)
                LDSM_X4(wh[n2][0], wh[n2][1], wh[n2][2], wh[n2][3],
                        wBase + so + n2 * 16 * PITCH_B);
#pragma unroll
            for (int mt = 0; mt < 4; ++mt)
#pragma unroll
                for (int nt = 0; nt < 4; ++nt)
                    MMA_FP16(acc[mt][nt], ah[mt],
                             wh[nt >> 1][nt & 1], wh[nt >> 1][(nt & 1) + 2]);
        }
    }

    const int group = lane >> 2;
    const int tcol  = (lane & 3) * 2;
#pragma unroll
    for (int mt = 0; mt < 4; ++mt) {
#pragma unroll
        for (int nt = 0; nt < 4; ++nt) {
            int row = m0 + wm * 64 + mt * 16 + group;
            int col = n0 + wn * 32 + nt * 8 + tcol;
            float bx = bias[col], by = bias[col + 1];
            float v00 = acc[mt][nt][0] + bx, v01 = acc[mt][nt][1] + by;
            float v10 = acc[mt][nt][2] + bx, v11 = acc[mt][nt][3] + by;
            if (MODE == 0) {
                *(float2*)(Cf + (size_t)row * DMODEL + col) = make_float2(v00, v01);
                *(float2*)(Cf + (size_t)(row + 8) * DMODEL + col) = make_float2(v10, v11);
            } else {
                v00 *= scale; v01 *= scale; v10 *= scale; v11 *= scale;
                int h = col >> 6, d = col & 63;
                int b0_ = row >> 11, s0_ = row & 2047;
                int b1_ = (row + 8) >> 11, s1_ = (row + 8) & 2047;
                *(uint32_t*)(Ch + (((size_t)(b0_ * NHEADS + h) * S_LEN + s0_) * DK) + d)
                    = pack_f16(v00, v01);
                *(uint32_t*)(Ch + (((size_t)(b1_ * NHEADS + h) * S_LEN + s1_) * DK) + d)
                    = pack_f16(v10, v11);
            }
        }
    }
}

__global__ void __launch_bounds__(256, 2) gemm_qkv(
    const float* __restrict__ bq, const float* __restrict__ bk,
    const float* __restrict__ bv)
{
    extern __shared__ __align__(128) char smem[];
    const int z = blockIdx.z;
    const float* bias = (z == 0) ? bq : (z == 1) ? bk : bv;
    const float scale = (z == 0) ? 0.125f : 1.0f;
    gemm_body_f16<1>(g_xf[z], g_wf[z], bias, nullptr, g_qkv[z], scale, smem);
}

__global__ void __launch_bounds__(256, 2) gemm_out(
    const float* __restrict__ bias, float* __restrict__ C)
{
    extern __shared__ __align__(128) char smem[];
    gemm_body_f16<0>(g_ctx, g_wf[3], bias, C, nullptr, 1.0f, smem);
}

// ======================= flash attention, fp16 in/out, 3-stage cp.async ====
// Exact-path shortcuts: warp-vote skip of o-rescale when row max unchanged,
// warp-ballot skip of mask application when no zeros. Bit-identical results.
#define APITCH    144
#define KV_STAGE  18432           // K 9216 + V 9216
#define AV_OFF    9216
#define QF_OFF    55296           // 3 * KV_STAGE
#define MASK_OFF  73728
#define ATTN_SMEM (MASK_OFF + 2 * 64 * 4)   // 74240

__global__ void __launch_bounds__(256, 2) attn_mma(
    const int* __restrict__ mask)
{
    extern __shared__ __align__(128) char smem[];
    const __half* Q = g_qkv[0];
    const __half* K = g_qkv[1];
    const __half* V = g_qkv[2];
    const uint32_t sb = smem_u32(smem);
    const int tid  = threadIdx.x;
    const int lane = tid & 31;
    const int wid  = tid >> 5;
    const int q0   = blockIdx.x * 128;
    const int h    = blockIdx.y;
    const int b    = blockIdx.z;
    const size_t base = (size_t)(b * NHEADS + h) * S_LEN * DK;

    const uint32_t laneOff = (uint32_t)((lane & 15) * APITCH + (lane >> 4) * 16);

    auto issue_kv = [&](int t) {
        int st = t % 3;
        const uint32_t sp = sb + (uint32_t)(st * KV_STAGE);
        const int k0 = t * 64;
#pragma unroll
        for (int i = 0; i < 2; ++i) {
            int slot = i * 256 + tid;
            int row  = slot >> 3;
            int g    = slot & 7;
            uint32_t soff = (uint32_t)(row * APITCH + g * 16);
            size_t goff = base + (size_t)(k0 + row) * DK + g * 8;
            CPA16(sp + soff,          K + goff);
            CPA16(sp + AV_OFF + soff, V + goff);
        }
        CP_COMMIT();
    };

#pragma unroll
    for (int i = 0; i < 4; ++i) {
        int slot = i * 256 + tid;
        int row  = slot >> 3;
        int g    = slot & 7;
        uint4 v = *(const uint4*)(Q + base + (size_t)(q0 + row) * DK + g * 8);
        *(uint4*)(smem + QF_OFF + row * APITCH + g * 16) = v;
    }
    issue_kv(0);
    issue_kv(1);
    __syncthreads();

    uint32_t qf[4][4];
    {
        const uint32_t qB = sb + QF_OFF + (uint32_t)(wid * 16) * APITCH + laneOff;
#pragma unroll
        for (int s = 0; s < 4; ++s)
            LDSM_X4(qf[s][0], qf[s][1], qf[s][2], qf[s][3], qB + s * 32);
    }

    float o[8][4];
#pragma unroll
    for (int dt = 0; dt < 8; ++dt)
#pragma unroll
        for (int r = 0; r < 4; ++r) o[dt][r] = 0.0f;
    float mi0 = -1.0e30f, mi1 = -1.0e30f, li0 = 0.0f, li1 = 0.0f;

#pragma unroll 1
    for (int t = 0; t < 32; ++t) {
        if (tid < 64)
            ((int*)(smem + MASK_OFF))[(t & 1) * 64 + tid] = mask[b * S_LEN + t * 64 + tid];
        if (t < 31) CP_WAIT1(); else CP_WAIT0();
        __syncthreads();
        if (t + 2 < 32) issue_kv(t + 2);

        const uint32_t kB = sb + (uint32_t)((t % 3) * KV_STAGE) + laneOff;

        // ---- S = Q K^T ----
        float s_[8][4];
#pragma unroll
        for (int nt = 0; nt < 8; ++nt)
#pragma unroll
            for (int r = 0; r < 4; ++r) s_[nt][r] = 0.0f;
#pragma unroll
        for (int st = 0; st < 4; ++st) {
#pragma unroll
            for (int g2 = 0; g2 < 4; ++g2) {
                uint32_t kf[4];
                LDSM_X4(kf[0], kf[1], kf[2], kf[3],
                        kB + g2 * (16 * APITCH) + st * 32);
                MMA_FP16(s_[2 * g2],     qf[st], kf[0], kf[2]);
                MMA_FP16(s_[2 * g2 + 1], qf[st], kf[1], kf[3]);
            }
        }

        // ---- mask (skipped via ballot when no zeros in this k-tile) ----
        const int* mbuf = (const int*)(smem + MASK_OFF) + (t & 1) * 64;
        {
            int2 mm = *(const int2*)&mbuf[lane * 2];   // 32 lanes cover 64 ints
            uint32_t anyz = __ballot_sync(0xffffffffu, (mm.x == 0) || (mm.y == 0));
            if (anyz) {
#pragma unroll
                for (int nt = 0; nt < 8; ++nt) {
                    int2 mv = *(const int2*)&mbuf[nt * 8 + (lane & 3) * 2];
                    if (mv.x == 0) { s_[nt][0] = -1.0e9f; s_[nt][2] = -1.0e9f; }
                    if (mv.y == 0) { s_[nt][1] = -1.0e9f; s_[nt][3] = -1.0e9f; }
                }
            }
        }

        // ---- online softmax ----
        float mx0 = -1.0e30f, mx1 = -1.0e30f;
#pragma unroll
        for (int nt = 0; nt < 8; ++nt) {
            mx0 = fmaxf(mx0, fmaxf(s_[nt][0], s_[nt][1]));
            mx1 = fmaxf(mx1, fmaxf(s_[nt][2], s_[nt][3]));
        }
        mx0 = fmaxf(mx0, __shfl_xor_sync(0xffffffffu, mx0, 1));
        mx0 = fmaxf(mx0, __shfl_xor_sync(0xffffffffu, mx0, 2));
        mx1 = fmaxf(mx1, __shfl_xor_sync(0xffffffffu, mx1, 1));
        mx1 = fmaxf(mx1, __shfl_xor_sync(0xffffffffu, mx1, 2));

        // rescale only if some row's max increased (warp-uniform vote);
        // otherwise alpha == exp(0) == 1 exactly -> identical results.
        bool nochg = (mx0 <= mi0) && (mx1 <= mi1);
        if (!__all_sync(0xffffffffu, nochg)) {
            const float mn0 = fmaxf(mi0, mx0), mn1 = fmaxf(mi1, mx1);
            const float a0 = __expf(mi0 - mn0), a1 = __expf(mi1 - mn1);
            li0 *= a0; li1 *= a1;
#pragma unroll
            for (int dt = 0; dt < 8; ++dt) {
                o[dt][0] *= a0; o[dt][1] *= a0;
                o[dt][2] *= a1; o[dt][3] *= a1;
            }
            mi0 = mn0; mi1 = mn1;
        }

        float sum0 = 0.0f, sum1 = 0.0f;
#pragma unroll
        for (int nt = 0; nt < 8; ++nt) {
            s_[nt][0] = __expf(s_[nt][0] - mi0);
            s_[nt][1] = __expf(s_[nt][1] - mi0);
            s_[nt][2] = __expf(s_[nt][2] - mi1);
            s_[nt][3] = __expf(s_[nt][3] - mi1);
            sum0 += s_[nt][0] + s_[nt][1];
            sum1 += s_[nt][2] + s_[nt][3];
        }
        sum0 += __shfl_xor_sync(0xffffffffu, sum0, 1);
        sum0 += __shfl_xor_sync(0xffffffffu, sum0, 2);
        sum1 += __shfl_xor_sync(0xffffffffu, sum1, 1);
        sum1 += __shfl_xor_sync(0xffffffffu, sum1, 2);
        li0 += sum0;
        li1 += sum1;

        // ---- O += P V ----
        const uint32_t vB = sb + (uint32_t)((t % 3) * KV_STAGE) + AV_OFF + laneOff;
#pragma unroll
        for (int st = 0; st < 4; ++st) {
            uint32_t pf[4];
            pf[0] = pack_f16(s_[2 * st][0],     s_[2 * st][1]);
            pf[1] = pack_f16(s_[2 * st][2],     s_[2 * st][3]);
            pf[2] = pack_f16(s_[2 * st + 1][0], s_[2 * st + 1][1]);
            pf[3] = pack_f16(s_[2 * st + 1][2], s_[2 * st + 1][3]);
#pragma unroll
            for (int j = 0; j < 4; ++j) {
                uint32_t vf[4];
                LDSM_X4_T(vf[0], vf[1], vf[2], vf[3],
                          vB + st * (16 * APITCH) + j * 32);
                MMA_FP16(o[2 * j],     pf, vf[0], vf[1]);
                MMA_FP16(o[2 * j + 1], pf, vf[2], vf[3]);
            }
        }
    }

    // ---- epilogue: normalize, write ctx fp16 (b, s, h*64+d) ----
    const int g  = lane >> 2;
    const int t2 = (lane & 3) * 2;
    const int row0 = q0 + wid * 16 + g;
    const int row1 = row0 + 8;
    const float inv0 = 1.0f / li0, inv1 = 1.0f / li1;
#pragma unroll
    for (int dt = 0; dt < 8; ++dt) {
        int col = h * DK + dt * 8 + t2;
        *(uint32_t*)(g_ctx + (size_t)(b * S_LEN + row0) * DMODEL + col) =
            pack_f16(o[dt][0] * inv0, o[dt][1] * inv0);
        *(uint32_t*)(g_ctx + (size_t)(b * S_LEN + row1) * DMODEL + col) =
            pack_f16(o[dt][2] * inv1, o[dt][3] * inv1);
    }
}

// ---------------------------------------------------------------------------
extern "C" void kernel_launch(void* const* d_in, const int* in_sizes, int n_in,
                              void* d_out, int out_size)
{
    const float* query = (const float*)d_in[0];
    const float* key   = (const float*)d_in[1];
    const float* value = (const float*)d_in[2];
    const int*   mask  = (const int*)d_in[3];
    const float* Wq = (const float*)d_in[4];
    const float* bq = (const float*)d_in[5];
    const float* Wk = (const float*)d_in[6];
    const float* bk = (const float*)d_in[7];
    const float* Wv = (const float*)d_in[8];
    const float* bv = (const float*)d_in[9];
    const float* Wo = (const float*)d_in[10];
    const float* bo = (const float*)d_in[11];
    float* out = (float*)d_out;

    cudaFuncSetAttribute(gemm_qkv, cudaFuncAttributeMaxDynamicSharedMemorySize, GEMM_SMEM);
    cudaFuncSetAttribute(gemm_out, cudaFuncAttributeMaxDynamicSharedMemorySize, GEMM_SMEM);
    cudaFuncSetAttribute(attn_mma, cudaFuncAttributeMaxDynamicSharedMemorySize, ATTN_SMEM);

    dim3 pg((MTOT * DMODEL / 4 + 255) / 256, 7);     // (4096, 7)
    prep_f16<<<pg, 256>>>(query, key, value, Wq, Wk, Wv, Wo);

    dim3 gq(DMODEL / 128, MTOT / 128, 3);            // (8, 32, 3) = 768 CTAs
    gemm_qkv<<<gq, 256, GEMM_SMEM>>>(bq, bk, bv);

    dim3 ag(S_LEN / 128, NHEADS, BATCH);             // (16, 16, 2) = 512 CTAs
    attn_mma<<<ag, 256, ATTN_SMEM>>>(mask);

    dim3 gg(DMODEL / 128, MTOT / 128);               // (8, 32) = 256 CTAs
    gemm_out<<<gg, 256, GEMM_SMEM>>>(bo, out);
}